// round 14
// baseline (speedup 1.0000x reference)
#include <cuda_runtime.h>
#include <cuda_bf16.h>

#define S_LEN 512
#define B_DIM 256
#define Z_DIM 64
#define BZ    ((size_t)B_DIM * Z_DIM)

// ---- packed f32x2 helpers (full fp32 precision, 2 MACs per instruction) ----
__device__ __forceinline__ unsigned long long pack2(float lo, float hi) {
    unsigned long long r;
    asm("mov.b64 %0, {%1, %2};" : "=l"(r) : "f"(lo), "f"(hi));
    return r;
}
__device__ __forceinline__ unsigned long long fma2(unsigned long long a,
                                                   unsigned long long b,
                                                   unsigned long long c) {
    unsigned long long d;
    asm("fma.rn.f32x2 %0, %1, %2, %3;" : "=l"(d) : "l"(a), "l"(b), "l"(c));
    return d;
}
__device__ __forceinline__ unsigned long long add2(unsigned long long a,
                                                   unsigned long long b) {
    unsigned long long d;
    asm("add.rn.f32x2 %0, %1, %2;" : "=l"(d) : "l"(a), "l"(b));
    return d;
}
__device__ __forceinline__ float hsum2(unsigned long long v) {
    float lo, hi;
    asm("mov.b64 {%0, %1}, %2;" : "=f"(lo), "=f"(hi) : "l"(v));
    return lo + hi;
}

// FFMA2 dot: 64-float smem vector (16 LDS.128) vs 32 packed T pairs (TP),
// 4 independent f32x2 chains of depth 8.
#define DOT64(VR, TP, result)                                                  \
    {                                                                          \
        const ulonglong2* p2 = reinterpret_cast<const ulonglong2*>(VR);        \
        unsigned long long s0 = 0, s1 = 0, s2 = 0, s3 = 0;                     \
        _Pragma("unroll")                                                      \
        for (int q = 0; q < 8; q++) {                                          \
            ulonglong2 u = p2[2 * q + 0];                                      \
            ulonglong2 w = p2[2 * q + 1];                                      \
            s0 = fma2(u.x, TP[4 * q + 0], s0);                                 \
            s1 = fma2(u.y, TP[4 * q + 1], s1);                                 \
            s2 = fma2(w.x, TP[4 * q + 2], s2);                                 \
            s3 = fma2(w.y, TP[4 * q + 3], s3);                                 \
        }                                                                      \
        result = hsum2(add2(add2(s0, s1), add2(s2, s3)));                      \
    }

// Warp-pair reduction of two values into ps[par] = {w0f, w0b, w1f, w1b}.
#define REDUCE2_TO_PS(par, abf, abb)                                           \
    {                                                                          \
        float sf = (abf), sb = (abb);                                          \
        _Pragma("unroll")                                                      \
        for (int o = 16; o > 0; o >>= 1) {                                     \
            sf += __shfl_xor_sync(0xffffffffu, sf, o);                         \
            sb += __shfl_xor_sync(0xffffffffu, sb, o);                         \
        }                                                                      \
        if ((z & 31) == 0) {                                                   \
            ps[par][2 * (z >> 5) + 0] = sf;                                    \
            ps[par][2 * (z >> 5) + 1] = sb;                                    \
        }                                                                      \
    }

// ---------------------------------------------------------------------------
// Paired fwd+bwd+posterior per CTA. 256 CTAs x 64 threads; CTA b runs both
// recursions of batch b (fwd slot k, bwd slot 511-k). Past the crossing
// (k>=257) each slot also emits two posterior rows: the missing factor is
// prefetched from gmem (written >=2 slots earlier by this same thread).
// All non-critical work (STGs, LDG prefetches, posterior math) lives in the
// post-barrier shadow.
// ---------------------------------------------------------------------------
__global__ __launch_bounds__(Z_DIM, 1)
void hmm_fb_kernel(const int* __restrict__ inp,      // [S, B]
                   const float* __restrict__ T,      // [Z, Z]
                   const float* __restrict__ pi,     // [Z]
                   const float* __restrict__ emit,   // [X, Z]
                   float* __restrict__ alpha,        // [S, B, Z]
                   float* __restrict__ beta,         // [S, B, Z]
                   float* __restrict__ post)         // [S, B, Z]
{
    const int b = blockIdx.x;
    const int z = threadIdx.x;

    __shared__ __align__(16) float vf[2][Z_DIM];
    __shared__ __align__(16) float vb[2][Z_DIM];
    __shared__ __align__(16) float ps[2][4];   // [slot parity]{w0f,w0b,w1f,w1b}
    __shared__ int x_sh[S_LEN];

    #pragma unroll
    for (int t = z; t < S_LEN; t += Z_DIM) x_sh[t] = inp[t * B_DIM + b];

    unsigned long long Tpf[Z_DIM / 2], Tpb[Z_DIM / 2];
    #pragma unroll
    for (int k = 0; k < Z_DIM; k += 4) {
        float4 v = *reinterpret_cast<const float4*>(&T[z * Z_DIM + k]);
        Tpf[k / 2]     = pack2(v.x, v.y);
        Tpf[k / 2 + 1] = pack2(v.z, v.w);
    }
    #pragma unroll
    for (int k = 0; k < Z_DIM; k += 2) {
        Tpb[k / 2] = pack2(T[k * Z_DIM + z], T[(k + 1) * Z_DIM + z]);
    }
    __syncthreads();            // x_sh visible before any use

    float* aw = alpha + (size_t)b * Z_DIM;
    float* bw = beta  + (size_t)b * Z_DIM;
    float* pw = post  + (size_t)b * Z_DIM;

    // ---- init: fwd t=0, bwd t=511 ----
    const float a0 = emit[x_sh[0] * Z_DIM + z] * pi[z];
    vf[0][z] = a0;
    float  f_pend = a0;
    size_t f_pofs = z;                                       // alpha[0]
    vb[1][z] = emit[x_sh[S_LEN - 1] * Z_DIM + z];            // c[511]
    float  b_pend = 1.0f;
    size_t b_pofs = (size_t)(S_LEN - 1) * BZ + z;            // beta[511]
    float Efo = emit[x_sh[1] * Z_DIM + z];
    float Efe = emit[x_sh[2] * Z_DIM + z];
    float Ebe = emit[x_sh[S_LEN - 2] * Z_DIM + z];
    float Ebo = emit[x_sh[S_LEN - 3] * Z_DIM + z];
    __syncthreads();

// Plain step (first half, no posterior)
#define STEP(tf, tb, FR, FW, BR, BW, EF, EB)                                   \
    {                                                                          \
        float df; DOT64(FR, Tpf, df);                                          \
        float db; DOT64(BR, Tpb, db);                                          \
        float nf = (EF) * df;                                                  \
        (FW)[z] = nf;                                                          \
        (BW)[z] = (EB) * db;                                                   \
        __syncthreads();                                                       \
        __stcs(&aw[f_pofs], f_pend);                                           \
        __stcs(&bw[b_pofs], b_pend);                                           \
        f_pend = nf; f_pofs = (size_t)(tf) * BZ + z;                           \
        b_pend = db; b_pofs = (size_t)(tb) * BZ + z;                           \
        EF = emit[x_sh[((tf) + 2 < S_LEN) ? (tf) + 2 : S_LEN - 1] * Z_DIM + z];\
        EB = emit[x_sh[((tb) >= 2) ? (tb) - 2 : 0] * Z_DIM + z];               \
    }

// Step with posterior production (second half). PW_/PR_ = ps write/read parity.
#define STEP_POST(tf, tb, FR, FW, BR, BW, EF, EB, BF, AB, PW_, PR_)            \
    {                                                                          \
        float df; DOT64(FR, Tpf, df);                                          \
        float db; DOT64(BR, Tpb, db);                                          \
        float nf = (EF) * df;                                                  \
        (FW)[z] = nf;                                                          \
        (BW)[z] = (EB) * db;                                                   \
        __syncthreads();                                                       \
        __stcs(&aw[f_pofs], f_pend);                                           \
        __stcs(&bw[b_pofs], b_pend);                                           \
        f_pend = nf; f_pofs = (size_t)(tf) * BZ + z;                           \
        b_pend = db; b_pofs = (size_t)(tb) * BZ + z;                           \
        /* flush previous slot's posterior rows (tf-1, tb+1) */                \
        {                                                                      \
            float4 v = *reinterpret_cast<const float4*>(ps[PR_]);              \
            __stcs(&pw[(size_t)((tf) - 1) * BZ + z], abf_p / (v.x + v.z));     \
            __stcs(&pw[(size_t)((tb) + 1) * BZ + z], abb_p / (v.y + v.w));     \
        }                                                                      \
        /* this slot's posterior partials (rows tf, tb) */                     \
        {                                                                      \
            float abf = nf * (BF);                                             \
            float abb = db * (AB);                                             \
            REDUCE2_TO_PS(PW_, abf, abb);                                      \
            abf_p = abf; abb_p = abb;                                          \
        }                                                                      \
        /* prefetch missing factors for slot+2 */                              \
        BF = __ldcs(&bw[(size_t)(((tf) + 2 < S_LEN) ? (tf) + 2 : S_LEN - 1) * BZ + z]); \
        AB = __ldcs(&aw[(size_t)(((tb) >= 2) ? (tb) - 2 : 0) * BZ + z]);       \
        EF = emit[x_sh[((tf) + 2 < S_LEN) ? (tf) + 2 : S_LEN - 1] * Z_DIM + z];\
        EB = emit[x_sh[((tb) >= 2) ? (tb) - 2 : 0] * Z_DIM + z];               \
    }

    // ---- first half: slots 1..256 (no posterior) ----
    for (int k = 1; k <= 255; k += 2) {
        STEP(k,     S_LEN - 1 - k, vf[0], vf[1], vb[1], vb[0], Efo, Ebe);
        STEP(k + 1, S_LEN - 2 - k, vf[1], vf[0], vb[0], vb[1], Efe, Ebo);
    }

    // ---- bridge: seed posterior pipeline with rows (256, 255) ----
    float abf_p, abb_p;
    float Bf_o, Bf_e, Ab_o, Ab_e;
    {
        // alpha[256] = f_pend (reg); beta[256] in gmem (STG'd slot 256).
        // beta[255]  = b_pend (reg); alpha[255] in gmem (STG'd slot 256).
        float B256 = bw[(size_t)256 * BZ + z];
        float A255 = aw[(size_t)255 * BZ + z];
        float abf = f_pend * B256;        // row 256
        float abb = b_pend * A255;        // row 255
        REDUCE2_TO_PS(0, abf, abb);       // par(256) = 0
        abf_p = abf; abb_p = abb;
        // prefetch for slots 257 (odd) and 258 (even)
        Bf_o = __ldcs(&bw[(size_t)257 * BZ + z]);
        Ab_o = __ldcs(&aw[(size_t)254 * BZ + z]);
        Bf_e = __ldcs(&bw[(size_t)258 * BZ + z]);
        Ab_e = __ldcs(&aw[(size_t)253 * BZ + z]);
    }

    // ---- second half: slots 257..510 (with posterior) ----
    for (int k = 257; k <= 509; k += 2) {
        STEP_POST(k,     S_LEN - 1 - k, vf[0], vf[1], vb[1], vb[0],
                  Efo, Ebe, Bf_o, Ab_o, 1, 0);
        STEP_POST(k + 1, S_LEN - 2 - k, vf[1], vf[0], vb[0], vb[1],
                  Efe, Ebo, Bf_e, Ab_e, 0, 1);
    }

    // ---- tail: fwd t=511, bwd t=0, posterior rows 510, 1, 511, 0 ----
    {
        float df; DOT64(vf[0], Tpf, df);   // fwd 511 reads vf[510&1=0]
        float db; DOT64(vb[1], Tpb, db);   // bwd 0 reads vb[1&1=1]
        float nf = Efo * df;               // Efo holds e[511]
        __stcs(&aw[f_pofs], f_pend);       // alpha[510]
        __stcs(&bw[b_pofs], b_pend);       // beta[1]
        __stcs(&aw[(size_t)(S_LEN - 1) * BZ + z], nf);   // alpha[511]
        __stcs(&bw[z], db);                              // beta[0]
        __syncthreads();                   // drain slot 510's ps[0] partials
        {
            float4 v = *reinterpret_cast<const float4*>(ps[0]);
            __stcs(&pw[(size_t)510 * BZ + z], abf_p / (v.x + v.z));
            __stcs(&pw[(size_t)1   * BZ + z], abb_p / (v.y + v.w));
        }
        float ab511 = nf;                  // beta[511] = 1
        float ab0   = a0 * db;             // alpha[0] * beta[0]
        REDUCE2_TO_PS(1, ab511, ab0);
        __syncthreads();
        {
            float4 v = *reinterpret_cast<const float4*>(ps[1]);
            __stcs(&pw[(size_t)(S_LEN - 1) * BZ + z], ab511 / (v.x + v.z));
            __stcs(&pw[z],                            ab0   / (v.y + v.w));
        }
    }
#undef STEP
#undef STEP_POST
}

extern "C" void kernel_launch(void* const* d_in, const int* in_sizes, int n_in,
                              void* d_out, int out_size)
{
    const int*   inp  = (const int*)  d_in[0];   // [512, 256] int32
    const float* T    = (const float*)d_in[1];   // [64, 64]
    const float* pi   = (const float*)d_in[2];   // [64]
    const float* emit = (const float*)d_in[3];   // [10000, 64]

    float* out   = (float*)d_out;
    const size_t N = (size_t)S_LEN * B_DIM * Z_DIM;
    float* alpha = out;
    float* beta  = out + N;
    float* post  = out + 2 * N;

    hmm_fb_kernel<<<B_DIM, Z_DIM>>>(inp, T, pi, emit, alpha, beta, post);
}

// round 15
// speedup vs baseline: 1.1959x; 1.1959x over previous
#include <cuda_runtime.h>
#include <cuda_bf16.h>

#define S_LEN 512
#define B_DIM 256
#define Z_DIM 64
#define BZ    ((size_t)B_DIM * Z_DIM)

// ---- packed f32x2 helpers (full fp32 precision, 2 MACs per instruction) ----
__device__ __forceinline__ unsigned long long pack2(float lo, float hi) {
    unsigned long long r;
    asm("mov.b64 %0, {%1, %2};" : "=l"(r) : "f"(lo), "f"(hi));
    return r;
}
__device__ __forceinline__ unsigned long long fma2(unsigned long long a,
                                                   unsigned long long b,
                                                   unsigned long long c) {
    unsigned long long d;
    asm("fma.rn.f32x2 %0, %1, %2, %3;" : "=l"(d) : "l"(a), "l"(b), "l"(c));
    return d;
}
__device__ __forceinline__ unsigned long long add2(unsigned long long a,
                                                   unsigned long long b) {
    unsigned long long d;
    asm("add.rn.f32x2 %0, %1, %2;" : "=l"(d) : "l"(a), "l"(b));
    return d;
}
__device__ __forceinline__ float hsum2(unsigned long long v) {
    float lo, hi;
    asm("mov.b64 {%0, %1}, %2;" : "=f"(lo), "=f"(hi) : "l"(v));
    return lo + hi;
}

// FFMA2 dot: 64-float smem vector (16 LDS.128) vs 32 packed T pairs (TP),
// 4 independent f32x2 chains of depth 8.
#define DOT64(VR, TP, result)                                                  \
    {                                                                          \
        const ulonglong2* p2 = reinterpret_cast<const ulonglong2*>(VR);        \
        unsigned long long s0 = 0, s1 = 0, s2 = 0, s3 = 0;                     \
        _Pragma("unroll")                                                      \
        for (int q = 0; q < 8; q++) {                                          \
            ulonglong2 u = p2[2 * q + 0];                                      \
            ulonglong2 w = p2[2 * q + 1];                                      \
            s0 = fma2(u.x, TP[4 * q + 0], s0);                                 \
            s1 = fma2(u.y, TP[4 * q + 1], s1);                                 \
            s2 = fma2(w.x, TP[4 * q + 2], s2);                                 \
            s3 = fma2(w.y, TP[4 * q + 3], s3);                                 \
        }                                                                      \
        result = hsum2(add2(add2(s0, s1), add2(s2, s3)));                      \
    }

// ---------------------------------------------------------------------------
// Paired fwd+bwd+posterior per CTA. 256 CTAs x 64 threads; CTA b runs both
// recursions of batch b (fwd slot k, bwd slot 511-k).
// KEY IDENTITY: sum_z alpha_t[z]*beta_t[z] is t-invariant (= likelihood), so
// ONE normalizer per batch, computed once at the crossing. The fused posterior
// is then 2 FMA + 2 STG + 2 prefetch LDG per slot — pure barrier-shadow work.
// ---------------------------------------------------------------------------
__global__ __launch_bounds__(Z_DIM, 1)
void hmm_fb_kernel(const int* __restrict__ inp,      // [S, B]
                   const float* __restrict__ T,      // [Z, Z]
                   const float* __restrict__ pi,     // [Z]
                   const float* __restrict__ emit,   // [X, Z]
                   float* __restrict__ alpha,        // [S, B, Z]
                   float* __restrict__ beta,         // [S, B, Z]
                   float* __restrict__ post)         // [S, B, Z]
{
    const int b = blockIdx.x;
    const int z = threadIdx.x;

    __shared__ __align__(16) float vf[2][Z_DIM];
    __shared__ __align__(16) float vb[2][Z_DIM];
    __shared__ float ls[2];                    // per-warp likelihood partials
    __shared__ int x_sh[S_LEN];

    #pragma unroll
    for (int t = z; t < S_LEN; t += Z_DIM) x_sh[t] = inp[t * B_DIM + b];

    unsigned long long Tpf[Z_DIM / 2], Tpb[Z_DIM / 2];
    #pragma unroll
    for (int k = 0; k < Z_DIM; k += 4) {
        float4 v = *reinterpret_cast<const float4*>(&T[z * Z_DIM + k]);
        Tpf[k / 2]     = pack2(v.x, v.y);
        Tpf[k / 2 + 1] = pack2(v.z, v.w);
    }
    #pragma unroll
    for (int k = 0; k < Z_DIM; k += 2) {
        Tpb[k / 2] = pack2(T[k * Z_DIM + z], T[(k + 1) * Z_DIM + z]);
    }
    __syncthreads();            // x_sh visible before any use

    float* aw = alpha + (size_t)b * Z_DIM;
    float* bw = beta  + (size_t)b * Z_DIM;
    float* pw = post  + (size_t)b * Z_DIM;

    // ---- init: fwd t=0, bwd t=511 ----
    const float a0 = emit[x_sh[0] * Z_DIM + z] * pi[z];
    vf[0][z] = a0;
    float  f_pend = a0;
    size_t f_pofs = z;                                       // alpha[0]
    vb[1][z] = emit[x_sh[S_LEN - 1] * Z_DIM + z];            // c[511]
    float  b_pend = 1.0f;
    size_t b_pofs = (size_t)(S_LEN - 1) * BZ + z;            // beta[511]
    float Efo = emit[x_sh[1] * Z_DIM + z];
    float Efe = emit[x_sh[2] * Z_DIM + z];
    float Ebe = emit[x_sh[S_LEN - 2] * Z_DIM + z];
    float Ebo = emit[x_sh[S_LEN - 3] * Z_DIM + z];
    __syncthreads();

// Plain step (first half, no posterior)
#define STEP(tf, tb, FR, FW, BR, BW, EF, EB)                                   \
    {                                                                          \
        float df; DOT64(FR, Tpf, df);                                          \
        float db; DOT64(BR, Tpb, db);                                          \
        float nf = (EF) * df;                                                  \
        (FW)[z] = nf;                                                          \
        (BW)[z] = (EB) * db;                                                   \
        __syncthreads();                                                       \
        __stcs(&aw[f_pofs], f_pend);                                           \
        __stcs(&bw[b_pofs], b_pend);                                           \
        f_pend = nf; f_pofs = (size_t)(tf) * BZ + z;                           \
        b_pend = db; b_pofs = (size_t)(tb) * BZ + z;                           \
        EF = emit[x_sh[((tf) + 2 < S_LEN) ? (tf) + 2 : S_LEN - 1] * Z_DIM + z];\
        EB = emit[x_sh[((tb) >= 2) ? (tb) - 2 : 0] * Z_DIM + z];               \
    }

// Step + posterior rows (tf, tb): factors BF=beta[tf], AB=alpha[tb] were
// prefetched two slots earlier; constant invL — no reductions, no divides.
#define STEP_POST(tf, tb, FR, FW, BR, BW, EF, EB, BF, AB)                      \
    {                                                                          \
        float df; DOT64(FR, Tpf, df);                                          \
        float db; DOT64(BR, Tpb, db);                                          \
        float nf = (EF) * df;                                                  \
        (FW)[z] = nf;                                                          \
        (BW)[z] = (EB) * db;                                                   \
        __syncthreads();                                                       \
        __stcs(&aw[f_pofs], f_pend);                                           \
        __stcs(&bw[b_pofs], b_pend);                                           \
        f_pend = nf; f_pofs = (size_t)(tf) * BZ + z;                           \
        b_pend = db; b_pofs = (size_t)(tb) * BZ + z;                           \
        __stcs(&pw[(size_t)(tf) * BZ + z], nf * (BF) * invL);                  \
        __stcs(&pw[(size_t)(tb) * BZ + z], db * (AB) * invL);                  \
        BF = __ldcs(&bw[(size_t)(((tf) + 2 < S_LEN) ? (tf) + 2 : S_LEN - 1) * BZ + z]); \
        AB = __ldcs(&aw[(size_t)(((tb) >= 2) ? (tb) - 2 : 0) * BZ + z]);       \
        EF = emit[x_sh[((tf) + 2 < S_LEN) ? (tf) + 2 : S_LEN - 1] * Z_DIM + z];\
        EB = emit[x_sh[((tb) >= 2) ? (tb) - 2 : 0] * Z_DIM + z];               \
    }

    // ---- first half: slots 1..256 (no posterior) ----
    for (int k = 1; k <= 255; k += 2) {
        STEP(k,     S_LEN - 1 - k, vf[0], vf[1], vb[1], vb[0], Efo, Ebe);
        STEP(k + 1, S_LEN - 2 - k, vf[1], vf[0], vb[0], vb[1], Efe, Ebo);
    }
    // State: f_pend=alpha[256], b_pend=beta[255]; gmem has alpha[<=255],
    // beta[>=256] (this thread's own STGs — program-order visible).

    // ---- bridge: one likelihood reduction; posterior rows 255, 256 ----
    float invL;
    float Bf_o, Bf_e, Ab_o, Ab_e;
    {
        float B256 = bw[(size_t)256 * BZ + z];   // beta[256]
        float A255 = aw[(size_t)255 * BZ + z];   // alpha[255]
        float abf = f_pend * B256;               // row 256 elementwise
        float s = abf;
        #pragma unroll
        for (int o = 16; o > 0; o >>= 1) s += __shfl_xor_sync(0xffffffffu, s, o);
        if ((z & 31) == 0) ls[z >> 5] = s;
        __syncthreads();
        invL = 1.0f / (ls[0] + ls[1]);           // likelihood (t-invariant)
        __stcs(&pw[(size_t)256 * BZ + z], abf * invL);
        __stcs(&pw[(size_t)255 * BZ + z], b_pend * A255 * invL);
        // prefetch factors for slots 257 (odd) and 258 (even)
        Bf_o = __ldcs(&bw[(size_t)257 * BZ + z]);
        Ab_o = __ldcs(&aw[(size_t)254 * BZ + z]);
        Bf_e = __ldcs(&bw[(size_t)258 * BZ + z]);
        Ab_e = __ldcs(&aw[(size_t)253 * BZ + z]);
    }

    // ---- second half: slots 257..510 (posterior in the barrier shadow) ----
    for (int k = 257; k <= 509; k += 2) {
        STEP_POST(k,     S_LEN - 1 - k, vf[0], vf[1], vb[1], vb[0],
                  Efo, Ebe, Bf_o, Ab_o);
        STEP_POST(k + 1, S_LEN - 2 - k, vf[1], vf[0], vb[0], vb[1],
                  Efe, Ebo, Bf_e, Ab_e);
    }

    // ---- tail: fwd t=511, bwd t=0; posterior rows 511, 0 ----
    {
        float df; DOT64(vf[0], Tpf, df);   // fwd 511 reads vf[510&1=0]
        float db; DOT64(vb[1], Tpb, db);   // bwd 0 reads vb[1&1=1]
        float nf = Efo * df;               // Efo holds e[511]
        __stcs(&aw[f_pofs], f_pend);       // alpha[510]
        __stcs(&bw[b_pofs], b_pend);       // beta[1]
        __stcs(&aw[(size_t)(S_LEN - 1) * BZ + z], nf);   // alpha[511]
        __stcs(&bw[z], db);                              // beta[0]
        __stcs(&pw[(size_t)(S_LEN - 1) * BZ + z], nf * invL);   // beta[511]=1
        __stcs(&pw[z], a0 * db * invL);                         // row 0
    }
#undef STEP
#undef STEP_POST
}

extern "C" void kernel_launch(void* const* d_in, const int* in_sizes, int n_in,
                              void* d_out, int out_size)
{
    const int*   inp  = (const int*)  d_in[0];   // [512, 256] int32
    const float* T    = (const float*)d_in[1];   // [64, 64]
    const float* pi   = (const float*)d_in[2];   // [64]
    const float* emit = (const float*)d_in[3];   // [10000, 64]

    float* out   = (float*)d_out;
    const size_t N = (size_t)S_LEN * B_DIM * Z_DIM;
    float* alpha = out;
    float* beta  = out + N;
    float* post  = out + 2 * N;

    hmm_fb_kernel<<<B_DIM, Z_DIM>>>(inp, T, pi, emit, alpha, beta, post);
}